// round 8
// baseline (speedup 1.0000x reference)
#include <cuda_runtime.h>
#include <cuda_bf16.h>
#include <cstdint>

#define N_NODES 50000
#define E_EDGES 800000
#define F_IN    128
#define F_OUT   64

// Static scratch
__device__ float g_support[N_NODES * F_OUT];   // (X@W)*t       12.8 MB
__device__ int   g_count[N_NODES];             // hist, then cursor
__device__ int   g_start[N_NODES + 1];         // CSR offsets
__device__ int2  g_edges[E_EDGES];             // (src, eval bits) sorted by dst

// ===========================================================================
// GEMM via mma.sync: A gmem->regs bf16 hi/lo split, B (W^T) split in-kernel
// into smem, ldmatrix. M=128/CTA, 8 warps, N=64, K=128.
// ===========================================================================
#define GT 256
#define ASTR 272
#define SM_BHI 0
#define SM_BLO (SM_BHI + 64 * ASTR)
#define SM_TOTAL (SM_BLO + 64 * ASTR)   // 34816

__device__ __forceinline__ uint32_t smem_u32(const void* p) {
    uint32_t a;
    asm("{ .reg .u64 tmp; cvta.to.shared.u64 tmp, %1; cvt.u32.u64 %0, tmp; }"
        : "=r"(a) : "l"(p));
    return a;
}

__device__ __forceinline__ void ldmatrix_x4(uint32_t* r, uint32_t addr) {
    asm volatile("ldmatrix.sync.aligned.m8n8.x4.shared.b16 {%0,%1,%2,%3}, [%4];"
                 : "=r"(r[0]), "=r"(r[1]), "=r"(r[2]), "=r"(r[3]) : "r"(addr));
}

__device__ __forceinline__ void mma_bf16(float* d, const uint32_t* a,
                                         const uint32_t* b) {
    asm volatile(
        "mma.sync.aligned.m16n8k16.row.col.f32.bf16.bf16.f32 "
        "{%0,%1,%2,%3}, {%4,%5,%6,%7}, {%8,%9}, {%0,%1,%2,%3};"
        : "+f"(d[0]), "+f"(d[1]), "+f"(d[2]), "+f"(d[3])
        : "r"(a[0]), "r"(a[1]), "r"(a[2]), "r"(a[3]), "r"(b[0]), "r"(b[1]));
}

__device__ __forceinline__ uint32_t pack_hi(float2 v) {
    __nv_bfloat162 h = __floats2bfloat162_rn(v.x, v.y);
    return *(uint32_t*)&h;
}
__device__ __forceinline__ uint32_t pack_lo(float2 v) {
    __nv_bfloat162 h = __floats2bfloat162_rn(v.x, v.y);
    float rx = v.x - __bfloat162float(__low2bfloat16(h));
    float ry = v.y - __bfloat162float(__high2bfloat16(h));
    __nv_bfloat162 l = __floats2bfloat162_rn(rx, ry);
    return *(uint32_t*)&l;
}

__global__ void __launch_bounds__(GT, 3)
gemm_tc_kernel(const float* __restrict__ x,
               const float* __restrict__ t,
               const float* __restrict__ weight)
{
    extern __shared__ char smem[];
    const uint32_t sb = smem_u32(smem);
    const int tid  = threadIdx.x;
    const int wid  = tid >> 5;
    const int lane = tid & 31;
    const int row0 = blockIdx.x * 128;

    // stage B = W^T hi/lo split in-kernel (weight[k][f] fp32, L2-hot)
    for (int i = tid; i < F_IN * F_OUT; i += GT) {
        int f = i & 63;
        int k = i >> 6;
        float v = weight[i];
        __nv_bfloat16 h = __float2bfloat16(v);
        __nv_bfloat16 l = __float2bfloat16(v - __bfloat162float(h));
        *(__nv_bfloat16*)(smem + SM_BHI + f * ASTR + k * 2) = h;
        *(__nv_bfloat16*)(smem + SM_BLO + f * ASTR + k * 2) = l;
    }
    __syncthreads();

    // A: direct gmem float2 loads in fragment layout
    const int g   = lane >> 2;
    const int tig = lane & 3;
    const int r0g = row0 + wid * 16 + g;
    const int r1g = r0g + 8;
    const bool v0 = r0g < N_NODES;
    const bool v1 = r1g < N_NODES;
    const float2* p0 = (const float2*)&x[(size_t)r0g * F_IN];
    const float2* p1 = (const float2*)&x[(size_t)r1g * F_IN];
    const float2 z2 = make_float2(0.f, 0.f);

    float acc[8][4];
    #pragma unroll
    for (int j = 0; j < 8; j++)
        #pragma unroll
        for (int q = 0; q < 4; q++)
            acc[j][q] = 0.0f;

    const int afrag = lane >> 3;
    const int arow  = lane & 7;

    float2 c00 = v0 ? p0[tig]     : z2;
    float2 c10 = v1 ? p1[tig]     : z2;
    float2 c01 = v0 ? p0[tig + 4] : z2;
    float2 c11 = v1 ? p1[tig + 4] : z2;

    #pragma unroll
    for (int kk = 0; kk < 8; kk++) {
        float2 n00, n10, n01, n11;
        if (kk < 7) {
            int o = (kk + 1) * 8 + tig;
            n00 = v0 ? p0[o]     : z2;
            n10 = v1 ? p1[o]     : z2;
            n01 = v0 ? p0[o + 4] : z2;
            n11 = v1 ? p1[o + 4] : z2;
        }

        uint32_t ahi[4], alo[4];
        ahi[0] = pack_hi(c00); alo[0] = pack_lo(c00);
        ahi[1] = pack_hi(c10); alo[1] = pack_lo(c10);
        ahi[2] = pack_hi(c01); alo[2] = pack_lo(c01);
        ahi[3] = pack_hi(c11); alo[3] = pack_lo(c11);

        #pragma unroll
        for (int j2 = 0; j2 < 4; j2++) {
            uint32_t b_off = (uint32_t)((j2 * 16 + (afrag >> 1) * 8 + arow) * ASTR
                                        + (kk * 16 + (afrag & 1) * 8) * 2);
            uint32_t bhi[4], blo[4];
            ldmatrix_x4(bhi, sb + SM_BHI + b_off);
            ldmatrix_x4(blo, sb + SM_BLO + b_off);

            mma_bf16(acc[j2 * 2 + 0], ahi, bhi + 0);
            mma_bf16(acc[j2 * 2 + 1], ahi, bhi + 2);
            mma_bf16(acc[j2 * 2 + 0], ahi, blo + 0);
            mma_bf16(acc[j2 * 2 + 1], ahi, blo + 2);
            mma_bf16(acc[j2 * 2 + 0], alo, bhi + 0);
            mma_bf16(acc[j2 * 2 + 1], alo, bhi + 2);
        }

        c00 = n00; c10 = n10; c01 = n01; c11 = n11;
    }

    int r0 = row0 + wid * 16 + (lane >> 2);
    int c0 = (lane & 3) * 2;
    float tv0 = 0.f, tv1 = 0.f;
    if (r0 < N_NODES)     tv0 = __ldg(&t[r0]);
    if (r0 + 8 < N_NODES) tv1 = __ldg(&t[r0 + 8]);

    #pragma unroll
    for (int j = 0; j < 8; j++) {
        if (r0 < N_NODES) {
            float2 v = make_float2(acc[j][0] * tv0, acc[j][1] * tv0);
            *(float2*)&g_support[(size_t)r0 * F_OUT + j * 8 + c0] = v;
        }
        if (r0 + 8 < N_NODES) {
            float2 v = make_float2(acc[j][2] * tv1, acc[j][3] * tv1);
            *(float2*)&g_support[(size_t)(r0 + 8) * F_OUT + j * 8 + c0] = v;
        }
    }
}

// ===========================================================================
// Sort pipeline: zero -> hist -> scan -> reorder
// ===========================================================================
__global__ void zero_kernel()
{
    int i = blockIdx.x * blockDim.x + threadIdx.x;
    if (i < N_NODES) g_count[i] = 0;
}

__global__ void hist_kernel(const int* __restrict__ dst)
{
    int e = blockIdx.x * blockDim.x + threadIdx.x;
    if (e < E_EDGES)
        atomicAdd(&g_count[__ldg(&dst[e])], 1);
}

// Single-CTA exclusive scan of g_count -> g_start (and cursor copy in g_count).
#define SCAN_T 1024
#define SCAN_CH 49               // 1024*49 = 50176 >= 50001
__global__ void __launch_bounds__(SCAN_T)
scan_kernel()
{
    __shared__ int ssum[SCAN_T];
    const int t = threadIdx.x;
    const int base = t * SCAN_CH;

    int local[SCAN_CH];
    int sum = 0;
    #pragma unroll
    for (int i = 0; i < SCAN_CH; i++) {
        int idx = base + i;
        local[i] = (idx < N_NODES) ? g_count[idx] : 0;
        sum += local[i];
    }
    ssum[t] = sum;
    __syncthreads();

    // Hillis-Steele inclusive scan over 1024 partials
    #pragma unroll
    for (int off = 1; off < SCAN_T; off <<= 1) {
        int v = (t >= off) ? ssum[t - off] : 0;
        __syncthreads();
        ssum[t] += v;
        __syncthreads();
    }
    int running = (t == 0) ? 0 : ssum[t - 1];

    #pragma unroll
    for (int i = 0; i < SCAN_CH; i++) {
        int idx = base + i;
        if (idx <= N_NODES) {
            g_start[idx] = running;
            if (idx < N_NODES) {
                g_count[idx] = running;      // cursor copy
                running += local[i];
            }
        }
    }
}

__global__ void reorder_kernel(const int* __restrict__ src,
                               const int* __restrict__ dst,
                               const float* __restrict__ edge_vals)
{
    int e = blockIdx.x * blockDim.x + threadIdx.x;
    if (e >= E_EDGES) return;
    int d  = __ldg(&dst[e]);
    int pos = atomicAdd(&g_count[d], 1);
    g_edges[pos] = make_int2(__ldg(&src[e]),
                             __float_as_int(__ldg(&edge_vals[e])));
}

// ===========================================================================
// Gather: 16 threads per node, each owns one float4 feature chunk.
// out[n] = bias + sum_{e in seg(n)} support[src_e] * val_e
// ===========================================================================
__global__ void __launch_bounds__(256)
gather_kernel(const float* __restrict__ bias,
              float* __restrict__ out)
{
    int gid = blockIdx.x * blockDim.x + threadIdx.x;
    int n = gid >> 4;
    int c = gid & 15;
    if (n >= N_NODES) return;

    int beg = __ldg(&g_start[n]);
    int end = __ldg(&g_start[n + 1]);

    float4 acc = *(const float4*)&bias[c * 4];

    for (int i = beg; i < end; i++) {
        int2 e = __ldg(&g_edges[i]);
        float ev = __int_as_float(e.y);
        float4 v = __ldg((const float4*)&g_support[(size_t)e.x * F_OUT] + c);
        acc.x += v.x * ev;
        acc.y += v.y * ev;
        acc.z += v.z * ev;
        acc.w += v.w * ev;
    }

    *((float4*)&out[(size_t)n * F_OUT] + c) = acc;
}

// ---------------------------------------------------------------------------
// Launch.  Inputs (metadata order): x, t, src, dst, edge_vals, weight, bias
// ---------------------------------------------------------------------------
extern "C" void kernel_launch(void* const* d_in, const int* in_sizes, int n_in,
                              void* d_out, int out_size)
{
    const float* x         = (const float*)d_in[0];
    const float* t         = (const float*)d_in[1];
    const int*   src       = (const int*)d_in[2];
    const int*   dst       = (const int*)d_in[3];
    const float* edge_vals = (const float*)d_in[4];
    const float* weight    = (const float*)d_in[5];
    const float* bias      = (const float*)d_in[6];
    float*       out       = (float*)d_out;

    cudaFuncSetAttribute(gemm_tc_kernel,
                         cudaFuncAttributeMaxDynamicSharedMemorySize, SM_TOTAL);

    // CSR build
    zero_kernel<<<(N_NODES + 255) / 256, 256>>>();
    hist_kernel<<<(E_EDGES + 255) / 256, 256>>>(dst);
    scan_kernel<<<1, SCAN_T>>>();
    reorder_kernel<<<(E_EDGES + 255) / 256, 256>>>(src, dst, edge_vals);

    // support = (X @ W) * t
    int gemm_blocks = (N_NODES + 127) / 128;            // 391
    gemm_tc_kernel<<<gemm_blocks, GT, SM_TOTAL>>>(x, t, weight);

    // out = bias + CSR-gather(support)
    long long gthreads = (long long)N_NODES * 16;
    int gblocks = (int)((gthreads + 255) / 256);        // 3125
    gather_kernel<<<gblocks, 256>>>(bias, out);
}

// round 9
// speedup vs baseline: 1.2848x; 1.2848x over previous
#include <cuda_runtime.h>
#include <cuda_bf16.h>
#include <cstdint>

#define N_NODES 50000
#define E_EDGES 800000
#define F_IN    128
#define F_OUT   64

// Static scratch
__device__ float g_support[N_NODES * F_OUT];   // (X@W)*t  12.8 MB
__device__ int   g_count[N_NODES];             // hist, then cursor
__device__ int   g_start[N_NODES + 1];         // CSR offsets
__device__ int   g_bsum[256];                  // per-block sums for scan
__device__ int2  g_edges[E_EDGES];             // (src, val bits) sorted by dst

#define SCAN_B 196                             // ceil(50000/256)

// ===========================================================================
// GEMM via mma.sync: A gmem->regs bf16 hi/lo split, B (W^T) split in-kernel
// into smem, ldmatrix. M=128/CTA, 8 warps, N=64, K=128.
// ===========================================================================
#define GT 256
#define ASTR 272
#define SM_BHI 0
#define SM_BLO (SM_BHI + 64 * ASTR)
#define SM_TOTAL (SM_BLO + 64 * ASTR)   // 34816

__device__ __forceinline__ uint32_t smem_u32(const void* p) {
    uint32_t a;
    asm("{ .reg .u64 tmp; cvta.to.shared.u64 tmp, %1; cvt.u32.u64 %0, tmp; }"
        : "=r"(a) : "l"(p));
    return a;
}

__device__ __forceinline__ void ldmatrix_x4(uint32_t* r, uint32_t addr) {
    asm volatile("ldmatrix.sync.aligned.m8n8.x4.shared.b16 {%0,%1,%2,%3}, [%4];"
                 : "=r"(r[0]), "=r"(r[1]), "=r"(r[2]), "=r"(r[3]) : "r"(addr));
}

__device__ __forceinline__ void mma_bf16(float* d, const uint32_t* a,
                                         const uint32_t* b) {
    asm volatile(
        "mma.sync.aligned.m16n8k16.row.col.f32.bf16.bf16.f32 "
        "{%0,%1,%2,%3}, {%4,%5,%6,%7}, {%8,%9}, {%0,%1,%2,%3};"
        : "+f"(d[0]), "+f"(d[1]), "+f"(d[2]), "+f"(d[3])
        : "r"(a[0]), "r"(a[1]), "r"(a[2]), "r"(a[3]), "r"(b[0]), "r"(b[1]));
}

__device__ __forceinline__ uint32_t pack_hi(float2 v) {
    __nv_bfloat162 h = __floats2bfloat162_rn(v.x, v.y);
    return *(uint32_t*)&h;
}
__device__ __forceinline__ uint32_t pack_lo(float2 v) {
    __nv_bfloat162 h = __floats2bfloat162_rn(v.x, v.y);
    float rx = v.x - __bfloat162float(__low2bfloat16(h));
    float ry = v.y - __bfloat162float(__high2bfloat16(h));
    __nv_bfloat162 l = __floats2bfloat162_rn(rx, ry);
    return *(uint32_t*)&l;
}

__global__ void __launch_bounds__(GT, 3)
gemm_tc_kernel(const float* __restrict__ x,
               const float* __restrict__ t,
               const float* __restrict__ weight)
{
    extern __shared__ char smem[];
    const uint32_t sb = smem_u32(smem);
    const int tid  = threadIdx.x;
    const int wid  = tid >> 5;
    const int lane = tid & 31;
    const int row0 = blockIdx.x * 128;

    for (int i = tid; i < F_IN * F_OUT; i += GT) {
        int f = i & 63;
        int k = i >> 6;
        float v = weight[i];
        __nv_bfloat16 h = __float2bfloat16(v);
        __nv_bfloat16 l = __float2bfloat16(v - __bfloat162float(h));
        *(__nv_bfloat16*)(smem + SM_BHI + f * ASTR + k * 2) = h;
        *(__nv_bfloat16*)(smem + SM_BLO + f * ASTR + k * 2) = l;
    }
    __syncthreads();

    const int g   = lane >> 2;
    const int tig = lane & 3;
    const int r0g = row0 + wid * 16 + g;
    const int r1g = r0g + 8;
    const bool v0 = r0g < N_NODES;
    const bool v1 = r1g < N_NODES;
    const float2* p0 = (const float2*)&x[(size_t)r0g * F_IN];
    const float2* p1 = (const float2*)&x[(size_t)r1g * F_IN];
    const float2 z2 = make_float2(0.f, 0.f);

    float acc[8][4];
    #pragma unroll
    for (int j = 0; j < 8; j++)
        #pragma unroll
        for (int q = 0; q < 4; q++)
            acc[j][q] = 0.0f;

    const int afrag = lane >> 3;
    const int arow  = lane & 7;

    float2 c00 = v0 ? p0[tig]     : z2;
    float2 c10 = v1 ? p1[tig]     : z2;
    float2 c01 = v0 ? p0[tig + 4] : z2;
    float2 c11 = v1 ? p1[tig + 4] : z2;

    #pragma unroll
    for (int kk = 0; kk < 8; kk++) {
        float2 n00, n10, n01, n11;
        if (kk < 7) {
            int o = (kk + 1) * 8 + tig;
            n00 = v0 ? p0[o]     : z2;
            n10 = v1 ? p1[o]     : z2;
            n01 = v0 ? p0[o + 4] : z2;
            n11 = v1 ? p1[o + 4] : z2;
        }

        uint32_t ahi[4], alo[4];
        ahi[0] = pack_hi(c00); alo[0] = pack_lo(c00);
        ahi[1] = pack_hi(c10); alo[1] = pack_lo(c10);
        ahi[2] = pack_hi(c01); alo[2] = pack_lo(c01);
        ahi[3] = pack_hi(c11); alo[3] = pack_lo(c11);

        #pragma unroll
        for (int j2 = 0; j2 < 4; j2++) {
            uint32_t b_off = (uint32_t)((j2 * 16 + (afrag >> 1) * 8 + arow) * ASTR
                                        + (kk * 16 + (afrag & 1) * 8) * 2);
            uint32_t bhi[4], blo[4];
            ldmatrix_x4(bhi, sb + SM_BHI + b_off);
            ldmatrix_x4(blo, sb + SM_BLO + b_off);

            mma_bf16(acc[j2 * 2 + 0], ahi, bhi + 0);
            mma_bf16(acc[j2 * 2 + 1], ahi, bhi + 2);
            mma_bf16(acc[j2 * 2 + 0], ahi, blo + 0);
            mma_bf16(acc[j2 * 2 + 1], ahi, blo + 2);
            mma_bf16(acc[j2 * 2 + 0], alo, bhi + 0);
            mma_bf16(acc[j2 * 2 + 1], alo, bhi + 2);
        }

        c00 = n00; c10 = n10; c01 = n01; c11 = n11;
    }

    int r0 = row0 + wid * 16 + (lane >> 2);
    int c0 = (lane & 3) * 2;
    float tv0 = 0.f, tv1 = 0.f;
    if (r0 < N_NODES)     tv0 = __ldg(&t[r0]);
    if (r0 + 8 < N_NODES) tv1 = __ldg(&t[r0 + 8]);

    #pragma unroll
    for (int j = 0; j < 8; j++) {
        if (r0 < N_NODES) {
            float2 v = make_float2(acc[j][0] * tv0, acc[j][1] * tv0);
            *(float2*)&g_support[(size_t)r0 * F_OUT + j * 8 + c0] = v;
        }
        if (r0 + 8 < N_NODES) {
            float2 v = make_float2(acc[j][2] * tv1, acc[j][3] * tv1);
            *(float2*)&g_support[(size_t)(r0 + 8) * F_OUT + j * 8 + c0] = v;
        }
    }
}

// ===========================================================================
// CSR build: zero -> hist -> scan1/scan2/scan3 -> reorder
// ===========================================================================
__global__ void zero_kernel()
{
    int i = blockIdx.x * blockDim.x + threadIdx.x;
    if (i < N_NODES) g_count[i] = 0;
}

__global__ void hist_kernel(const int* __restrict__ dst)
{
    int e = (blockIdx.x * blockDim.x + threadIdx.x) * 4;
    if (e + 3 < E_EDGES) {
        int4 d = *(const int4*)&dst[e];
        atomicAdd(&g_count[d.x], 1);
        atomicAdd(&g_count[d.y], 1);
        atomicAdd(&g_count[d.z], 1);
        atomicAdd(&g_count[d.w], 1);
    } else {
        for (int i = e; i < E_EDGES; i++)
            atomicAdd(&g_count[__ldg(&dst[i])], 1);
    }
}

// exclusive block scan over 256 threads; returns exclusive prefix of v
__device__ __forceinline__ int block_exscan256(int v)
{
    const int tid = threadIdx.x;
    const int lane = tid & 31;
    const int w = tid >> 5;
    int x = v;
    #pragma unroll
    for (int off = 1; off < 32; off <<= 1) {
        int y = __shfl_up_sync(0xFFFFFFFFu, x, off);
        if (lane >= off) x += y;
    }
    __shared__ int wsum[8];
    if (lane == 31) wsum[w] = x;
    __syncthreads();
    if (w == 0 && lane < 8) {
        int s = wsum[lane];
        #pragma unroll
        for (int off = 1; off < 8; off <<= 1) {
            int y = __shfl_up_sync(0xFFu, s, off);
            if (lane >= off) s += y;
        }
        wsum[lane] = s;
    }
    __syncthreads();
    int woff = (w == 0) ? 0 : wsum[w - 1];
    return woff + x - v;
}

__global__ void __launch_bounds__(256)
scan1_kernel()     // per-block sums of g_count
{
    int idx = blockIdx.x * 256 + threadIdx.x;
    int v = (idx < N_NODES) ? g_count[idx] : 0;
    int ex = block_exscan256(v);
    if (threadIdx.x == 255) g_bsum[blockIdx.x] = ex + v;
}

__global__ void __launch_bounds__(256)
scan2_kernel()     // exclusive scan of SCAN_B block sums
{
    int tid = threadIdx.x;
    int v = (tid < SCAN_B) ? g_bsum[tid] : 0;
    int ex = block_exscan256(v);
    if (tid < SCAN_B) g_bsum[tid] = ex;
}

__global__ void __launch_bounds__(256)
scan3_kernel()     // final offsets + cursor copy
{
    int idx = blockIdx.x * 256 + threadIdx.x;
    int v = (idx < N_NODES) ? g_count[idx] : 0;
    int ex = block_exscan256(v) + g_bsum[blockIdx.x];
    if (idx <= N_NODES) g_start[idx] = ex;
    if (idx < N_NODES)  g_count[idx] = ex;
}

__global__ void __launch_bounds__(256)
reorder_kernel(const int* __restrict__ src,
               const int* __restrict__ dst,
               const float* __restrict__ edge_vals)
{
    int e = (blockIdx.x * blockDim.x + threadIdx.x) * 4;
    if (e + 3 < E_EDGES) {
        int4   s = *(const int4*)&src[e];
        int4   d = *(const int4*)&dst[e];
        float4 v = *(const float4*)&edge_vals[e];
        int p0 = atomicAdd(&g_count[d.x], 1);
        int p1 = atomicAdd(&g_count[d.y], 1);
        int p2 = atomicAdd(&g_count[d.z], 1);
        int p3 = atomicAdd(&g_count[d.w], 1);
        g_edges[p0] = make_int2(s.x, __float_as_int(v.x));
        g_edges[p1] = make_int2(s.y, __float_as_int(v.y));
        g_edges[p2] = make_int2(s.z, __float_as_int(v.z));
        g_edges[p3] = make_int2(s.w, __float_as_int(v.w));
    } else {
        for (int i = e; i < E_EDGES; i++) {
            int d = __ldg(&dst[i]);
            int p = atomicAdd(&g_count[d], 1);
            g_edges[p] = make_int2(__ldg(&src[i]),
                                   __float_as_int(__ldg(&edge_vals[i])));
        }
    }
}

// ===========================================================================
// Gather: one warp per node.  Lane owns float2 of the 64 features.
// out[n] = bias + sum_{e in seg(n)} support[src_e] * val_e
// ===========================================================================
__global__ void __launch_bounds__(256)
gather_kernel(const float* __restrict__ bias,
              float* __restrict__ out)
{
    int gwarp = (blockIdx.x * blockDim.x + threadIdx.x) >> 5;
    int lane  = threadIdx.x & 31;
    if (gwarp >= N_NODES) return;

    int beg = __ldg(&g_start[gwarp]);
    int end = __ldg(&g_start[gwarp + 1]);

    float2 acc = *(const float2*)&bias[lane * 2];

    #pragma unroll 4
    for (int i = beg; i < end; i++) {
        int2 e = __ldg(&g_edges[i]);                 // warp-uniform broadcast
        float ev = __int_as_float(e.y);
        float2 v = __ldg((const float2*)&g_support[(size_t)e.x * F_OUT] + lane);
        acc.x += v.x * ev;
        acc.y += v.y * ev;
    }

    *((float2*)&out[(size_t)gwarp * F_OUT] + lane) = acc;
}

// ---------------------------------------------------------------------------
// Launch.  Inputs (metadata order): x, t, src, dst, edge_vals, weight, bias
// ---------------------------------------------------------------------------
extern "C" void kernel_launch(void* const* d_in, const int* in_sizes, int n_in,
                              void* d_out, int out_size)
{
    const float* x         = (const float*)d_in[0];
    const float* t         = (const float*)d_in[1];
    const int*   src       = (const int*)d_in[2];
    const int*   dst       = (const int*)d_in[3];
    const float* edge_vals = (const float*)d_in[4];
    const float* weight    = (const float*)d_in[5];
    const float* bias      = (const float*)d_in[6];
    float*       out       = (float*)d_out;

    cudaFuncSetAttribute(gemm_tc_kernel,
                         cudaFuncAttributeMaxDynamicSharedMemorySize, SM_TOTAL);

    // support = (X @ W) * t
    int gemm_blocks = (N_NODES + 127) / 128;            // 391
    gemm_tc_kernel<<<gemm_blocks, GT, SM_TOTAL>>>(x, t, weight);

    // CSR build
    zero_kernel<<<(N_NODES + 255) / 256, 256>>>();
    int equads = (E_EDGES / 4 + 255) / 256;             // 782 blocks
    hist_kernel<<<equads, 256>>>(dst);
    scan1_kernel<<<SCAN_B, 256>>>();
    scan2_kernel<<<1, 256>>>();
    scan3_kernel<<<SCAN_B, 256>>>();
    reorder_kernel<<<equads, 256>>>(src, dst, edge_vals);

    // out = bias + CSR-gather(support)
    long long gthreads = (long long)N_NODES * 32;
    int gblocks = (int)((gthreads + 255) / 256);        // 6250
    gather_kernel<<<gblocks, 256>>>(bias, out);
}

// round 10
// speedup vs baseline: 1.5434x; 1.2013x over previous
#include <cuda_runtime.h>
#include <cuda_bf16.h>
#include <cstdint>

#define N_NODES 50000
#define E_EDGES 800000
#define F_IN    128
#define F_OUT   64

// Static scratch
__device__ float g_support[N_NODES * F_OUT];   // (X@W)*t  12.8 MB
__device__ int   g_count[N_NODES];             // hist, then cursor
__device__ int   g_start[N_NODES + 1];         // CSR offsets
__device__ int   g_bsum[256];                  // block sums for scan
__device__ int2  g_edges[E_EDGES];             // (src, val bits) sorted by dst

// grid barrier state (count self-resets every barrier -> replay-deterministic)
__device__ int g_bar_count;
__device__ int g_bar_gen;

#define FB 444                                 // fused-kernel blocks (148*3)
#define SCAN_B 196                             // ceil(50000/256)

// ===========================================================================
// GEMM via mma.sync: A gmem->regs bf16 hi/lo split, B (W^T) split in-kernel
// into smem, ldmatrix. M=128/CTA, 8 warps, N=64, K=128. (proven R8/R9)
// ===========================================================================
#define GT 256
#define ASTR 272
#define SM_BHI 0
#define SM_BLO (SM_BHI + 64 * ASTR)
#define SM_TOTAL (SM_BLO + 64 * ASTR)   // 34816

__device__ __forceinline__ uint32_t smem_u32(const void* p) {
    uint32_t a;
    asm("{ .reg .u64 tmp; cvta.to.shared.u64 tmp, %1; cvt.u32.u64 %0, tmp; }"
        : "=r"(a) : "l"(p));
    return a;
}

__device__ __forceinline__ void ldmatrix_x4(uint32_t* r, uint32_t addr) {
    asm volatile("ldmatrix.sync.aligned.m8n8.x4.shared.b16 {%0,%1,%2,%3}, [%4];"
                 : "=r"(r[0]), "=r"(r[1]), "=r"(r[2]), "=r"(r[3]) : "r"(addr));
}

__device__ __forceinline__ void mma_bf16(float* d, const uint32_t* a,
                                         const uint32_t* b) {
    asm volatile(
        "mma.sync.aligned.m16n8k16.row.col.f32.bf16.bf16.f32 "
        "{%0,%1,%2,%3}, {%4,%5,%6,%7}, {%8,%9}, {%0,%1,%2,%3};"
        : "+f"(d[0]), "+f"(d[1]), "+f"(d[2]), "+f"(d[3])
        : "r"(a[0]), "r"(a[1]), "r"(a[2]), "r"(a[3]), "r"(b[0]), "r"(b[1]));
}

__device__ __forceinline__ uint32_t pack_hi(float2 v) {
    __nv_bfloat162 h = __floats2bfloat162_rn(v.x, v.y);
    return *(uint32_t*)&h;
}
__device__ __forceinline__ uint32_t pack_lo(float2 v) {
    __nv_bfloat162 h = __floats2bfloat162_rn(v.x, v.y);
    float rx = v.x - __bfloat162float(__low2bfloat16(h));
    float ry = v.y - __bfloat162float(__high2bfloat16(h));
    __nv_bfloat162 l = __floats2bfloat162_rn(rx, ry);
    return *(uint32_t*)&l;
}

__global__ void __launch_bounds__(GT, 3)
gemm_tc_kernel(const float* __restrict__ x,
               const float* __restrict__ t,
               const float* __restrict__ weight)
{
    extern __shared__ char smem[];
    const uint32_t sb = smem_u32(smem);
    const int tid  = threadIdx.x;
    const int wid  = tid >> 5;
    const int lane = tid & 31;
    const int row0 = blockIdx.x * 128;

    for (int i = tid; i < F_IN * F_OUT; i += GT) {
        int f = i & 63;
        int k = i >> 6;
        float v = weight[i];
        __nv_bfloat16 h = __float2bfloat16(v);
        __nv_bfloat16 l = __float2bfloat16(v - __bfloat162float(h));
        *(__nv_bfloat16*)(smem + SM_BHI + f * ASTR + k * 2) = h;
        *(__nv_bfloat16*)(smem + SM_BLO + f * ASTR + k * 2) = l;
    }
    __syncthreads();

    const int g   = lane >> 2;
    const int tig = lane & 3;
    const int r0g = row0 + wid * 16 + g;
    const int r1g = r0g + 8;
    const bool v0 = r0g < N_NODES;
    const bool v1 = r1g < N_NODES;
    const float2* p0 = (const float2*)&x[(size_t)r0g * F_IN];
    const float2* p1 = (const float2*)&x[(size_t)r1g * F_IN];
    const float2 z2 = make_float2(0.f, 0.f);

    float acc[8][4];
    #pragma unroll
    for (int j = 0; j < 8; j++)
        #pragma unroll
        for (int q = 0; q < 4; q++)
            acc[j][q] = 0.0f;

    const int afrag = lane >> 3;
    const int arow  = lane & 7;

    float2 c00 = v0 ? p0[tig]     : z2;
    float2 c10 = v1 ? p1[tig]     : z2;
    float2 c01 = v0 ? p0[tig + 4] : z2;
    float2 c11 = v1 ? p1[tig + 4] : z2;

    #pragma unroll
    for (int kk = 0; kk < 8; kk++) {
        float2 n00, n10, n01, n11;
        if (kk < 7) {
            int o = (kk + 1) * 8 + tig;
            n00 = v0 ? p0[o]     : z2;
            n10 = v1 ? p1[o]     : z2;
            n01 = v0 ? p0[o + 4] : z2;
            n11 = v1 ? p1[o + 4] : z2;
        }

        uint32_t ahi[4], alo[4];
        ahi[0] = pack_hi(c00); alo[0] = pack_lo(c00);
        ahi[1] = pack_hi(c10); alo[1] = pack_lo(c10);
        ahi[2] = pack_hi(c01); alo[2] = pack_lo(c01);
        ahi[3] = pack_hi(c11); alo[3] = pack_lo(c11);

        #pragma unroll
        for (int j2 = 0; j2 < 4; j2++) {
            uint32_t b_off = (uint32_t)((j2 * 16 + (afrag >> 1) * 8 + arow) * ASTR
                                        + (kk * 16 + (afrag & 1) * 8) * 2);
            uint32_t bhi[4], blo[4];
            ldmatrix_x4(bhi, sb + SM_BHI + b_off);
            ldmatrix_x4(blo, sb + SM_BLO + b_off);

            mma_bf16(acc[j2 * 2 + 0], ahi, bhi + 0);
            mma_bf16(acc[j2 * 2 + 1], ahi, bhi + 2);
            mma_bf16(acc[j2 * 2 + 0], ahi, blo + 0);
            mma_bf16(acc[j2 * 2 + 1], ahi, blo + 2);
            mma_bf16(acc[j2 * 2 + 0], alo, bhi + 0);
            mma_bf16(acc[j2 * 2 + 1], alo, bhi + 2);
        }

        c00 = n00; c10 = n10; c01 = n01; c11 = n11;
    }

    int r0 = row0 + wid * 16 + (lane >> 2);
    int c0 = (lane & 3) * 2;
    float tv0 = 0.f, tv1 = 0.f;
    if (r0 < N_NODES)     tv0 = __ldg(&t[r0]);
    if (r0 + 8 < N_NODES) tv1 = __ldg(&t[r0 + 8]);

    #pragma unroll
    for (int j = 0; j < 8; j++) {
        if (r0 < N_NODES) {
            float2 v = make_float2(acc[j][0] * tv0, acc[j][1] * tv0);
            *(float2*)&g_support[(size_t)r0 * F_OUT + j * 8 + c0] = v;
        }
        if (r0 + 8 < N_NODES) {
            float2 v = make_float2(acc[j][2] * tv1, acc[j][3] * tv1);
            *(float2*)&g_support[(size_t)(r0 + 8) * F_OUT + j * 8 + c0] = v;
        }
    }
}

// ===========================================================================
// Fused CSR build + gather (persistent, 444 co-resident blocks, spin barrier)
// ===========================================================================
__device__ __forceinline__ void grid_barrier()
{
    __syncthreads();
    if (threadIdx.x == 0) {
        __threadfence();                                    // release
        int gen = *(volatile int*)&g_bar_gen;
        int arrived = atomicAdd(&g_bar_count, 1);
        if (arrived == FB - 1) {
            g_bar_count = 0;
            __threadfence();
            atomicAdd(&g_bar_gen, 1);
        } else {
            while (*(volatile int*)&g_bar_gen == gen)
                __nanosleep(64);
        }
        __threadfence();                                    // acquire
    }
    __syncthreads();
}

// exclusive block scan over 256 threads; returns exclusive prefix of v
__device__ __forceinline__ int block_exscan256(int v)
{
    const int tid = threadIdx.x;
    const int lane = tid & 31;
    const int w = tid >> 5;
    int x = v;
    #pragma unroll
    for (int off = 1; off < 32; off <<= 1) {
        int y = __shfl_up_sync(0xFFFFFFFFu, x, off);
        if (lane >= off) x += y;
    }
    __shared__ int wsum[8];
    if (lane == 31) wsum[w] = x;
    __syncthreads();
    if (w == 0 && lane < 8) {
        int s = wsum[lane];
        #pragma unroll
        for (int off = 1; off < 8; off <<= 1) {
            int y = __shfl_up_sync(0xFFu, s, off);
            if (lane >= off) s += y;
        }
        wsum[lane] = s;
    }
    __syncthreads();
    int woff = (w == 0) ? 0 : wsum[w - 1];
    int r = woff + x - v;
    __syncthreads();               // wsum reused across phases
    return r;
}

__global__ void __launch_bounds__(256, 3)
fused_agg_kernel(const int* __restrict__ src,
                 const int* __restrict__ dst,
                 const float* __restrict__ edge_vals,
                 const float* __restrict__ bias,
                 float* __restrict__ out)
{
    const int tid = threadIdx.x;
    const int bid = blockIdx.x;
    const int gthread = bid * 256 + tid;
    const int nthreads = FB * 256;

    // P0: zero counters
    for (int i = gthread; i < N_NODES; i += nthreads)
        g_count[i] = 0;
    grid_barrier();

    // P1: histogram of dst (int4 quads; E % 4 == 0)
    for (int q = gthread; q < E_EDGES / 4; q += nthreads) {
        int4 d = __ldg((const int4*)dst + q);
        atomicAdd(&g_count[d.x], 1);
        atomicAdd(&g_count[d.y], 1);
        atomicAdd(&g_count[d.z], 1);
        atomicAdd(&g_count[d.w], 1);
    }
    grid_barrier();

    // P2a: per-block partial scans (blocks 0..SCAN_B-1 own 256 nodes each)
    if (bid < SCAN_B) {
        int idx = bid * 256 + tid;
        int v = (idx < N_NODES) ? __ldcg(&g_count[idx]) : 0;
        int ex = block_exscan256(v);
        if (tid == 255) g_bsum[bid] = ex + v;
    }
    grid_barrier();

    // P2b: scan the block sums
    if (bid == 0) {
        int v = (tid < SCAN_B) ? __ldcg(&g_bsum[tid]) : 0;
        int ex = block_exscan256(v);
        if (tid < SCAN_B) g_bsum[tid] = ex;
    }
    grid_barrier();

    // P2c: final offsets + cursor copy
    if (bid < SCAN_B) {
        int idx = bid * 256 + tid;
        int v = (idx < N_NODES) ? __ldcg(&g_count[idx]) : 0;
        int ex = block_exscan256(v) + __ldcg(&g_bsum[bid]);
        if (idx < N_NODES) {
            g_start[idx] = ex;
            g_count[idx] = ex;
        }
    }
    if (gthread == 0) g_start[N_NODES] = E_EDGES;
    grid_barrier();

    // P3: reorder edges by dst
    for (int q = gthread; q < E_EDGES / 4; q += nthreads) {
        int4   s = __ldg((const int4*)src + q);
        int4   d = __ldg((const int4*)dst + q);
        float4 v = __ldg((const float4*)edge_vals + q);
        int p0 = atomicAdd(&g_count[d.x], 1);
        int p1 = atomicAdd(&g_count[d.y], 1);
        int p2 = atomicAdd(&g_count[d.z], 1);
        int p3 = atomicAdd(&g_count[d.w], 1);
        g_edges[p0] = make_int2(s.x, __float_as_int(v.x));
        g_edges[p1] = make_int2(s.y, __float_as_int(v.y));
        g_edges[p2] = make_int2(s.z, __float_as_int(v.z));
        g_edges[p3] = make_int2(s.w, __float_as_int(v.w));
    }
    grid_barrier();

    // P4: gather — one warp per node, lane owns a float2 of the 64 features
    {
        const int lane  = tid & 31;
        const int wid   = gthread >> 5;
        const int nwrp  = nthreads >> 5;
        float2 bv = *(const float2*)&bias[lane * 2];

        for (int n = wid; n < N_NODES; n += nwrp) {
            int beg = __ldcg(&g_start[n]);
            int end = __ldcg(&g_start[n + 1]);
            float2 acc = bv;
            for (int i = beg; i < end; i++) {
                int2 e = __ldcg(&g_edges[i]);           // warp-uniform
                float ev = __int_as_float(e.y);
                float2 v = __ldg((const float2*)&g_support[(size_t)e.x * F_OUT] + lane);
                acc.x += v.x * ev;
                acc.y += v.y * ev;
            }
            *((float2*)&out[(size_t)n * F_OUT] + lane) = acc;
        }
    }
}

// ---------------------------------------------------------------------------
// Launch.  Inputs (metadata order): x, t, src, dst, edge_vals, weight, bias
// ---------------------------------------------------------------------------
extern "C" void kernel_launch(void* const* d_in, const int* in_sizes, int n_in,
                              void* d_out, int out_size)
{
    const float* x         = (const float*)d_in[0];
    const float* t         = (const float*)d_in[1];
    const int*   src       = (const int*)d_in[2];
    const int*   dst       = (const int*)d_in[3];
    const float* edge_vals = (const float*)d_in[4];
    const float* weight    = (const float*)d_in[5];
    const float* bias      = (const float*)d_in[6];
    float*       out       = (float*)d_out;

    cudaFuncSetAttribute(gemm_tc_kernel,
                         cudaFuncAttributeMaxDynamicSharedMemorySize, SM_TOTAL);

    // 1. support = (X @ W) * t
    int gemm_blocks = (N_NODES + 127) / 128;            // 391
    gemm_tc_kernel<<<gemm_blocks, GT, SM_TOTAL>>>(x, t, weight);

    // 2. fused CSR build + gather (out = bias + A @ support)
    fused_agg_kernel<<<FB, 256>>>(src, dst, edge_vals, bias, out);
}

// round 11
// speedup vs baseline: 1.7596x; 1.1401x over previous
#include <cuda_runtime.h>
#include <cuda_bf16.h>
#include <cstdint>

#define N_NODES 50000
#define E_EDGES 800000
#define F_IN    128
#define F_OUT   64

// Static scratch
__device__ float g_support[N_NODES * F_OUT];   // (X@W)*t  12.8 MB
__device__ int   g_count[N_NODES];             // hist, then cursor (re-zeroed in P4)
__device__ int   g_start[N_NODES + 1];         // CSR offsets
__device__ int   g_bsum[256];                  // block sums for scan
__device__ int2  g_edges[E_EDGES];             // (src, val bits) sorted by dst

// grid barrier state (count self-resets every barrier -> replay-deterministic)
__device__ int g_bar_count;
__device__ int g_bar_gen;

#define FB 444                                 // persistent blocks (148*3)
#define GEMM_B 391                             // ceil(50000/128)
#define SCAN_B 196                             // ceil(50000/256)

#define GT 256
#define ASTR 272
#define SM_BHI 0
#define SM_BLO (SM_BHI + 64 * ASTR)
#define SM_TOTAL (SM_BLO + 64 * ASTR)          // 34816 dynamic smem

// ---------------------------------------------------------------------------
// helpers
// ---------------------------------------------------------------------------
__device__ __forceinline__ uint32_t smem_u32(const void* p) {
    uint32_t a;
    asm("{ .reg .u64 tmp; cvta.to.shared.u64 tmp, %1; cvt.u32.u64 %0, tmp; }"
        : "=r"(a) : "l"(p));
    return a;
}

__device__ __forceinline__ void ldmatrix_x4(uint32_t* r, uint32_t addr) {
    asm volatile("ldmatrix.sync.aligned.m8n8.x4.shared.b16 {%0,%1,%2,%3}, [%4];"
                 : "=r"(r[0]), "=r"(r[1]), "=r"(r[2]), "=r"(r[3]) : "r"(addr));
}

__device__ __forceinline__ void mma_bf16(float* d, const uint32_t* a,
                                         const uint32_t* b) {
    asm volatile(
        "mma.sync.aligned.m16n8k16.row.col.f32.bf16.bf16.f32 "
        "{%0,%1,%2,%3}, {%4,%5,%6,%7}, {%8,%9}, {%0,%1,%2,%3};"
        : "+f"(d[0]), "+f"(d[1]), "+f"(d[2]), "+f"(d[3])
        : "r"(a[0]), "r"(a[1]), "r"(a[2]), "r"(a[3]), "r"(b[0]), "r"(b[1]));
}

__device__ __forceinline__ uint32_t pack_hi(float2 v) {
    __nv_bfloat162 h = __floats2bfloat162_rn(v.x, v.y);
    return *(uint32_t*)&h;
}
__device__ __forceinline__ uint32_t pack_lo(float2 v) {
    __nv_bfloat162 h = __floats2bfloat162_rn(v.x, v.y);
    float rx = v.x - __bfloat162float(__low2bfloat16(h));
    float ry = v.y - __bfloat162float(__high2bfloat16(h));
    __nv_bfloat162 l = __floats2bfloat162_rn(rx, ry);
    return *(uint32_t*)&l;
}

__device__ __forceinline__ void grid_barrier()
{
    __syncthreads();
    if (threadIdx.x == 0) {
        __threadfence();                                    // release
        int gen = *(volatile int*)&g_bar_gen;
        int arrived = atomicAdd(&g_bar_count, 1);
        if (arrived == FB - 1) {
            g_bar_count = 0;
            __threadfence();
            atomicAdd(&g_bar_gen, 1);
        } else {
            while (*(volatile int*)&g_bar_gen == gen)
                __nanosleep(64);
        }
        __threadfence();                                    // acquire
    }
    __syncthreads();
}

// exclusive block scan over 256 threads; returns exclusive prefix of v
__device__ __forceinline__ int block_exscan256(int v)
{
    const int tid = threadIdx.x;
    const int lane = tid & 31;
    const int w = tid >> 5;
    int x = v;
    #pragma unroll
    for (int off = 1; off < 32; off <<= 1) {
        int y = __shfl_up_sync(0xFFFFFFFFu, x, off);
        if (lane >= off) x += y;
    }
    __shared__ int wsum[8];
    if (lane == 31) wsum[w] = x;
    __syncthreads();
    if (w == 0 && lane < 8) {
        int s = wsum[lane];
        #pragma unroll
        for (int off = 1; off < 8; off <<= 1) {
            int y = __shfl_up_sync(0xFFu, s, off);
            if (lane >= off) s += y;
        }
        wsum[lane] = s;
    }
    __syncthreads();
    int woff = (w == 0) ? 0 : wsum[w - 1];
    int r = woff + x - v;
    __syncthreads();
    return r;
}

// ---------------------------------------------------------------------------
// GEMM tile (phase-1 body): support[row0..row0+127][:] = (x@W)*t
// ---------------------------------------------------------------------------
__device__ void gemm_tile(char* smem, uint32_t sb, int row0,
                          const float* __restrict__ x,
                          const float* __restrict__ t,
                          const float* __restrict__ weight)
{
    const int tid  = threadIdx.x;
    const int wid  = tid >> 5;
    const int lane = tid & 31;

    for (int i = tid; i < F_IN * F_OUT; i += GT) {
        int f = i & 63;
        int k = i >> 6;
        float v = __ldg(&weight[i]);
        __nv_bfloat16 h = __float2bfloat16(v);
        __nv_bfloat16 l = __float2bfloat16(v - __bfloat162float(h));
        *(__nv_bfloat16*)(smem + SM_BHI + f * ASTR + k * 2) = h;
        *(__nv_bfloat16*)(smem + SM_BLO + f * ASTR + k * 2) = l;
    }
    __syncthreads();

    const int g   = lane >> 2;
    const int tig = lane & 3;
    const int r0g = row0 + wid * 16 + g;
    const int r1g = r0g + 8;
    const bool v0 = r0g < N_NODES;
    const bool v1 = r1g < N_NODES;
    const float2* p0 = (const float2*)&x[(size_t)r0g * F_IN];
    const float2* p1 = (const float2*)&x[(size_t)r1g * F_IN];
    const float2 z2 = make_float2(0.f, 0.f);

    float acc[8][4];
    #pragma unroll
    for (int j = 0; j < 8; j++)
        #pragma unroll
        for (int q = 0; q < 4; q++)
            acc[j][q] = 0.0f;

    const int afrag = lane >> 3;
    const int arow  = lane & 7;

    float2 c00 = v0 ? p0[tig]     : z2;
    float2 c10 = v1 ? p1[tig]     : z2;
    float2 c01 = v0 ? p0[tig + 4] : z2;
    float2 c11 = v1 ? p1[tig + 4] : z2;

    #pragma unroll
    for (int kk = 0; kk < 8; kk++) {
        float2 n00, n10, n01, n11;
        if (kk < 7) {
            int o = (kk + 1) * 8 + tig;
            n00 = v0 ? p0[o]     : z2;
            n10 = v1 ? p1[o]     : z2;
            n01 = v0 ? p0[o + 4] : z2;
            n11 = v1 ? p1[o + 4] : z2;
        }

        uint32_t ahi[4], alo[4];
        ahi[0] = pack_hi(c00); alo[0] = pack_lo(c00);
        ahi[1] = pack_hi(c10); alo[1] = pack_lo(c10);
        ahi[2] = pack_hi(c01); alo[2] = pack_lo(c01);
        ahi[3] = pack_hi(c11); alo[3] = pack_lo(c11);

        #pragma unroll
        for (int j2 = 0; j2 < 4; j2++) {
            uint32_t b_off = (uint32_t)((j2 * 16 + (afrag >> 1) * 8 + arow) * ASTR
                                        + (kk * 16 + (afrag & 1) * 8) * 2);
            uint32_t bhi[4], blo[4];
            ldmatrix_x4(bhi, sb + SM_BHI + b_off);
            ldmatrix_x4(blo, sb + SM_BLO + b_off);

            mma_bf16(acc[j2 * 2 + 0], ahi, bhi + 0);
            mma_bf16(acc[j2 * 2 + 1], ahi, bhi + 2);
            mma_bf16(acc[j2 * 2 + 0], ahi, blo + 0);
            mma_bf16(acc[j2 * 2 + 1], ahi, blo + 2);
            mma_bf16(acc[j2 * 2 + 0], alo, bhi + 0);
            mma_bf16(acc[j2 * 2 + 1], alo, bhi + 2);
        }

        c00 = n00; c10 = n10; c01 = n01; c11 = n11;
    }

    int r0 = row0 + wid * 16 + (lane >> 2);
    int c0 = (lane & 3) * 2;
    float tv0 = 0.f, tv1 = 0.f;
    if (r0 < N_NODES)     tv0 = __ldg(&t[r0]);
    if (r0 + 8 < N_NODES) tv1 = __ldg(&t[r0 + 8]);

    #pragma unroll
    for (int j = 0; j < 8; j++) {
        if (r0 < N_NODES) {
            float2 v = make_float2(acc[j][0] * tv0, acc[j][1] * tv0);
            *(float2*)&g_support[(size_t)r0 * F_OUT + j * 8 + c0] = v;
        }
        if (r0 + 8 < N_NODES) {
            float2 v = make_float2(acc[j][2] * tv1, acc[j][3] * tv1);
            *(float2*)&g_support[(size_t)(r0 + 8) * F_OUT + j * 8 + c0] = v;
        }
    }
}

// ---------------------------------------------------------------------------
// ONE persistent kernel: GEMM+hist -> scan -> reorder -> gather
// ---------------------------------------------------------------------------
__global__ void __launch_bounds__(256, 3)
fused_all_kernel(const float* __restrict__ x,
                 const float* __restrict__ t,
                 const int* __restrict__ src,
                 const int* __restrict__ dst,
                 const float* __restrict__ edge_vals,
                 const float* __restrict__ weight,
                 const float* __restrict__ bias,
                 float* __restrict__ out)
{
    extern __shared__ char smem[];
    const uint32_t sb = smem_u32(smem);
    const int tid = threadIdx.x;
    const int bid = blockIdx.x;
    const int gthread = bid * 256 + tid;
    const int nthreads = FB * 256;

    // P1a: GEMM tile (blocks 0..GEMM_B-1).  g_count is zero on entry
    // (module-load init on run 1; re-zeroed in P4 on every run).
    if (bid < GEMM_B)
        gemm_tile(smem, sb, bid * 128, x, t, weight);

    // P1b: histogram of dst (all blocks, int4 quads; E % 4 == 0)
    for (int q = gthread; q < E_EDGES / 4; q += nthreads) {
        int4 d = __ldg((const int4*)dst + q);
        atomicAdd(&g_count[d.x], 1);
        atomicAdd(&g_count[d.y], 1);
        atomicAdd(&g_count[d.z], 1);
        atomicAdd(&g_count[d.w], 1);
    }
    grid_barrier();

    // P2a: per-block partial scans
    if (bid < SCAN_B) {
        int idx = bid * 256 + tid;
        int v = (idx < N_NODES) ? __ldcg(&g_count[idx]) : 0;
        int ex = block_exscan256(v);
        if (tid == 255) g_bsum[bid] = ex + v;
    }
    grid_barrier();

    // P2b: scan the block sums
    if (bid == 0) {
        int v = (tid < SCAN_B) ? __ldcg(&g_bsum[tid]) : 0;
        int ex = block_exscan256(v);
        if (tid < SCAN_B) g_bsum[tid] = ex;
    }
    grid_barrier();

    // P2c: final offsets + cursor copy
    if (bid < SCAN_B) {
        int idx = bid * 256 + tid;
        int v = (idx < N_NODES) ? __ldcg(&g_count[idx]) : 0;
        int ex = block_exscan256(v) + __ldcg(&g_bsum[bid]);
        if (idx < N_NODES) {
            g_start[idx] = ex;
            g_count[idx] = ex;
        }
    }
    if (gthread == 0) g_start[N_NODES] = E_EDGES;
    grid_barrier();

    // P3: reorder edges by dst
    for (int q = gthread; q < E_EDGES / 4; q += nthreads) {
        int4   s = __ldg((const int4*)src + q);
        int4   d = __ldg((const int4*)dst + q);
        float4 v = __ldg((const float4*)edge_vals + q);
        int p0 = atomicAdd(&g_count[d.x], 1);
        int p1 = atomicAdd(&g_count[d.y], 1);
        int p2 = atomicAdd(&g_count[d.z], 1);
        int p3 = atomicAdd(&g_count[d.w], 1);
        g_edges[p0] = make_int2(s.x, __float_as_int(v.x));
        g_edges[p1] = make_int2(s.y, __float_as_int(v.y));
        g_edges[p2] = make_int2(s.z, __float_as_int(v.z));
        g_edges[p3] = make_int2(s.w, __float_as_int(v.w));
    }
    grid_barrier();

    // P4a: re-zero g_count for the next graph replay (nobody reads it again)
    for (int i = gthread; i < N_NODES; i += nthreads)
        g_count[i] = 0;

    // P4b: gather — one warp per node, lane owns float2; 4-edge unroll for MLP
    {
        const int lane  = tid & 31;
        const int wrp   = gthread >> 5;
        const int nwrp  = nthreads >> 5;
        float2 bv = *(const float2*)&bias[lane * 2];

        for (int n = wrp; n < N_NODES; n += nwrp) {
            int beg = __ldg(&g_start[n]);
            int end = __ldg(&g_start[n + 1]);
            float2 acc = bv;
            int i = beg;
            for (; i + 4 <= end; i += 4) {
                int2 e0 = __ldg(&g_edges[i]);
                int2 e1 = __ldg(&g_edges[i + 1]);
                int2 e2 = __ldg(&g_edges[i + 2]);
                int2 e3 = __ldg(&g_edges[i + 3]);
                float2 s0 = __ldg((const float2*)&g_support[(size_t)e0.x * F_OUT] + lane);
                float2 s1 = __ldg((const float2*)&g_support[(size_t)e1.x * F_OUT] + lane);
                float2 s2 = __ldg((const float2*)&g_support[(size_t)e2.x * F_OUT] + lane);
                float2 s3 = __ldg((const float2*)&g_support[(size_t)e3.x * F_OUT] + lane);
                acc.x += s0.x * __int_as_float(e0.y);
                acc.y += s0.y * __int_as_float(e0.y);
                acc.x += s1.x * __int_as_float(e1.y);
                acc.y += s1.y * __int_as_float(e1.y);
                acc.x += s2.x * __int_as_float(e2.y);
                acc.y += s2.y * __int_as_float(e2.y);
                acc.x += s3.x * __int_as_float(e3.y);
                acc.y += s3.y * __int_as_float(e3.y);
            }
            for (; i < end; i++) {
                int2 e = __ldg(&g_edges[i]);
                float ev = __int_as_float(e.y);
                float2 v = __ldg((const float2*)&g_support[(size_t)e.x * F_OUT] + lane);
                acc.x += v.x * ev;
                acc.y += v.y * ev;
            }
            *((float2*)&out[(size_t)n * F_OUT] + lane) = acc;
        }
    }
}

// ---------------------------------------------------------------------------
// Launch.  Inputs (metadata order): x, t, src, dst, edge_vals, weight, bias
// ---------------------------------------------------------------------------
extern "C" void kernel_launch(void* const* d_in, const int* in_sizes, int n_in,
                              void* d_out, int out_size)
{
    const float* x         = (const float*)d_in[0];
    const float* t         = (const float*)d_in[1];
    const int*   src       = (const int*)d_in[2];
    const int*   dst       = (const int*)d_in[3];
    const float* edge_vals = (const float*)d_in[4];
    const float* weight    = (const float*)d_in[5];
    const float* bias      = (const float*)d_in[6];
    float*       out       = (float*)d_out;

    fused_all_kernel<<<FB, 256, SM_TOTAL>>>(x, t, src, dst, edge_vals,
                                            weight, bias, out);
}